// round 11
// baseline (speedup 1.0000x reference)
#include <cuda_runtime.h>
#include <cuda_bf16.h>
#include <cstdint>
#include <cstddef>
#include <math.h>

#define BQ 4
#define TT 512
#define BT (BQ * TT)      // 2048
#define DD 512
#define HH 1024
#define GG (4 * HH)       // 4096
#define VV 50000
#define VPAD 50048        // 391 * 128
#define NCTA 128          // persistent LSTM CTAs

using ull = unsigned long long;

// ---------------- packed f32x2 helpers ----------------
__device__ __forceinline__ ull pk2(float v) {
    ull r; asm("mov.b64 %0, {%1,%2};" : "=l"(r) : "f"(v), "f"(v)); return r;
}
__device__ __forceinline__ void unpk(float& lo, float& hi, ull v) {
    asm("mov.b64 {%0,%1}, %2;" : "=f"(lo), "=f"(hi) : "l"(v));
}
#define FMA2(acc, a, b) \
    asm("fma.rn.f32x2 %0, %1, %2, %0;" : "+l"(acc) : "l"(a), "l"(b))

// ---------------- device scratch ----------------
__device__ float g_xg[(size_t)BT * GG];
__device__ float g_h0[(size_t)BT * HH];
__device__ float g_h1[(size_t)BT * HH];
__device__ float g_hT[2 * HH * BQ];
__device__ float g_lse[BT];
__device__ unsigned g_flags[TT * NCTA];             // per-(step,cta) barrier flags
__device__ __nv_bfloat16 g_wb[(size_t)VPAD * HH];   // bf16 W_out, padded
__device__ __nv_bfloat16 g_hb[(size_t)BT * HH];     // bf16 h1

// zero the 512x128 flag array (grid 256x256 covers it exactly)
__global__ __launch_bounds__(256) void zero_flags() {
    g_flags[blockIdx.x * 256 + threadIdx.x] = 0u;
}

// ---------------------------------------------------------------------------
// f32 -> bf16 conversion (zero-pads tail rows for W)
// ---------------------------------------------------------------------------
__global__ __launch_bounds__(256) void conv_bf16(
    const float* __restrict__ src, __nv_bfloat16* __restrict__ dst,
    size_t n_src, size_t n_total)
{
    const size_t i = ((size_t)blockIdx.x * 256 + threadIdx.x) * 4;
    if (i >= n_total) return;
    uint2 o;
    if (i < n_src) {
        const float4 v = *(const float4*)(src + i);
        __nv_bfloat162 lo = __floats2bfloat162_rn(v.x, v.y);
        __nv_bfloat162 hi = __floats2bfloat162_rn(v.z, v.w);
        o.x = *(unsigned*)&lo;
        o.y = *(unsigned*)&hi;
    } else {
        o.x = 0u; o.y = 0u;
    }
    *(uint2*)(dst + i) = o;
}

// ---------------------------------------------------------------------------
// mma.sync bf16 GEMM with cp.async double buffering (unchanged from R10 WIN)
// ---------------------------------------------------------------------------
__device__ __forceinline__ uint32_t smem_u32(const void* p) {
    uint32_t a;
    asm("{ .reg .u64 t; cvta.to.shared.u64 t, %1; cvt.u32.u64 %0, t; }"
        : "=r"(a) : "l"(p));
    return a;
}
#define LDSM_X4(r0, r1, r2, r3, addr) \
    asm volatile("ldmatrix.sync.aligned.m8n8.x4.shared.b16 {%0,%1,%2,%3}, [%4];" \
        : "=r"(r0), "=r"(r1), "=r"(r2), "=r"(r3) : "r"(addr))
#define MMA16816(c, a0, a1, a2, a3, b0, b1) \
    asm volatile("mma.sync.aligned.m16n8k16.row.col.f32.bf16.bf16.f32 " \
        "{%0,%1,%2,%3}, {%4,%5,%6,%7}, {%8,%9}, {%0,%1,%2,%3};" \
        : "+f"((c)[0]), "+f"((c)[1]), "+f"((c)[2]), "+f"((c)[3]) \
        : "r"(a0), "r"(a1), "r"(a2), "r"(a3), "r"(b0), "r"(b1))
#define CP16(saddr, gptr) \
    asm volatile("cp.async.cg.shared.global [%0], [%1], 16;" \
        :: "r"(saddr), "l"(gptr))

#define MMA_SMEM 65536   // 2 bufs x (16KB A + 16KB B)

__global__ __launch_bounds__(256, 2) void gemm_mma(
    const __nv_bfloat16* __restrict__ A,   // [2048][1024]
    const __nv_bfloat16* __restrict__ B,   // [50048][1024]
    const float* __restrict__ bias, float* __restrict__ C)
{
    extern __shared__ __align__(16) char smem_mma[];
    const uint32_t smb = smem_u32(smem_mma);

    const int tid = threadIdx.x;
    const int bm = blockIdx.x, bn = blockIdx.y;
    const int lane = tid & 31, wid = tid >> 5;
    const int wm = wid & 3, wn = wid >> 2;
    const int g = lane >> 3, l8 = lane & 7;

    float acc[2][8][4];
#pragma unroll
    for (int mt = 0; mt < 2; ++mt)
#pragma unroll
        for (int nt = 0; nt < 8; ++nt)
#pragma unroll
            for (int q = 0; q < 4; ++q) acc[mt][nt][q] = 0.f;

    const int arow0 = wm * 32 + (g & 1) * 8 + l8;
    const int aug   = g >> 1;
    const int brow0 = wn * 64 + (g >> 1) * 8 + l8;
    const int bug   = g & 1;

    const int lrow = tid >> 3, lunit = tid & 7;
    const __nv_bfloat16* Abase = A + (size_t)(bm * 128) * HH;
    const __nv_bfloat16* Bbase = B + (size_t)(bn * 128) * HH;

    int rowv[4];
    uint32_t soff[4];
#pragma unroll
    for (int i = 0; i < 4; ++i) {
        rowv[i] = lrow + i * 32;
        soff[i] = (uint32_t)rowv[i] * 128u
                + ((uint32_t)(lunit ^ (rowv[i] & 7)) << 4);
    }

    auto issue_chunk = [&](int kc, int buf) {
        const uint32_t ab = smb + (uint32_t)buf * 32768u;
        const uint32_t bb = ab + 16384u;
#pragma unroll
        for (int i = 0; i < 4; ++i) {
            CP16(ab + soff[i],
                 Abase + (size_t)rowv[i] * HH + kc * 64 + lunit * 8);
            CP16(bb + soff[i],
                 Bbase + (size_t)rowv[i] * HH + kc * 64 + lunit * 8);
        }
    };

    issue_chunk(0, 0);
    asm volatile("cp.async.commit_group;" ::: "memory");

    for (int kc = 0; kc < HH / 64; ++kc) {
        const int buf = kc & 1;
        if (kc + 1 < HH / 64) {
            issue_chunk(kc + 1, buf ^ 1);
            asm volatile("cp.async.commit_group;" ::: "memory");
            asm volatile("cp.async.wait_group 1;" ::: "memory");
        } else {
            asm volatile("cp.async.wait_group 0;" ::: "memory");
        }
        __syncthreads();

        const uint32_t asmb = smb + (uint32_t)buf * 32768u;
        const uint32_t bsmb = asmb + 16384u;
#pragma unroll
        for (int ks = 0; ks < 4; ++ks) {
            uint32_t a[2][4];
#pragma unroll
            for (int mt = 0; mt < 2; ++mt) {
                const int row = arow0 + mt * 16;
                const uint32_t addr = asmb + (uint32_t)row * 128u
                    + ((uint32_t)((ks * 2 + aug) ^ l8) << 4);
                LDSM_X4(a[mt][0], a[mt][1], a[mt][2], a[mt][3], addr);
            }
#pragma unroll
            for (int p = 0; p < 4; ++p) {
                const int row = brow0 + p * 16;
                const uint32_t addr = bsmb + (uint32_t)row * 128u
                    + ((uint32_t)((ks * 2 + bug) ^ l8) << 4);
                uint32_t b0, b1, b2, b3;
                LDSM_X4(b0, b1, b2, b3, addr);
                MMA16816(acc[0][2 * p],     a[0][0], a[0][1], a[0][2], a[0][3], b0, b1);
                MMA16816(acc[0][2 * p + 1], a[0][0], a[0][1], a[0][2], a[0][3], b2, b3);
                MMA16816(acc[1][2 * p],     a[1][0], a[1][1], a[1][2], a[1][3], b0, b1);
                MMA16816(acc[1][2 * p + 1], a[1][0], a[1][1], a[1][2], a[1][3], b2, b3);
            }
        }
        __syncthreads();
    }

    const int mrow = lane >> 2, nc2 = (lane & 3) * 2;
#pragma unroll
    for (int mt = 0; mt < 2; ++mt) {
        const int row0 = bm * 128 + wm * 32 + mt * 16 + mrow;
        float* c0 = C + (size_t)row0 * VV;
        float* c1 = C + (size_t)(row0 + 8) * VV;
#pragma unroll
        for (int nt = 0; nt < 8; ++nt) {
            const int col = bn * 128 + wn * 64 + nt * 8 + nc2;
            if (col < VV) {
                const float bx = __ldg(bias + col);
                const float by = __ldg(bias + col + 1);
                *(float2*)(c0 + col) =
                    make_float2(acc[mt][nt][0] + bx, acc[mt][nt][1] + by);
                *(float2*)(c1 + col) =
                    make_float2(acc[mt][nt][2] + bx, acc[mt][nt][3] + by);
            }
        }
    }
}

// ---------------------------------------------------------------------------
// SIMT f32x2 GEMM (K1/K3) — unchanged
// ---------------------------------------------------------------------------
#define SA 132

__global__ __launch_bounds__(256) void gemm_tn(
    const float* __restrict__ A, const float* __restrict__ B,
    const float* __restrict__ bias, float* __restrict__ C,
    int M, int N, int K,
    const int* __restrict__ gatherIdx, const float* __restrict__ Xsrc)
{
    __shared__ __align__(16) float As[16 * SA];
    __shared__ __align__(16) float Bs[16 * SA];

    const int tid = threadIdx.x;
    const int bn = blockIdx.x, bm = blockIdx.y;
    const int tx = tid & 15, ty = tid >> 4;

    ull acc[8][4];
#pragma unroll
    for (int i = 0; i < 8; ++i)
#pragma unroll
        for (int j = 0; j < 4; ++j) acc[i][j] = 0ull;

    const int m0 = tid >> 2;
    const int k4 = tid & 3;

    const int gm0 = bm * 128 + m0;
    const int gm1 = gm0 + 64;
    const float* arow0;
    const float* arow1;
    if (gatherIdx) {
        arow0 = Xsrc + (size_t)gatherIdx[gm0] * K;
        arow1 = Xsrc + (size_t)gatherIdx[gm1] * K;
    } else {
        arow0 = A + (size_t)gm0 * K;
        arow1 = A + (size_t)gm1 * K;
    }
    const int gn0 = bn * 128 + m0;
    const int gn1 = gn0 + 64;
    const bool bv0 = gn0 < N, bv1 = gn1 < N;
    const float* brow0 = B + (size_t)gn0 * K;
    const float* brow1 = B + (size_t)gn1 * K;
    const float4 z4 = make_float4(0.f, 0.f, 0.f, 0.f);

    for (int kt = 0; kt < K; kt += 16) {
        float4 a0 = *(const float4*)(arow0 + kt + k4 * 4);
        float4 a1 = *(const float4*)(arow1 + kt + k4 * 4);
        float4 b0 = bv0 ? *(const float4*)(brow0 + kt + k4 * 4) : z4;
        float4 b1 = bv1 ? *(const float4*)(brow1 + kt + k4 * 4) : z4;

        __syncthreads();
        As[(k4 * 4 + 0) * SA + m0] = a0.x;
        As[(k4 * 4 + 1) * SA + m0] = a0.y;
        As[(k4 * 4 + 2) * SA + m0] = a0.z;
        As[(k4 * 4 + 3) * SA + m0] = a0.w;
        As[(k4 * 4 + 0) * SA + m0 + 64] = a1.x;
        As[(k4 * 4 + 1) * SA + m0 + 64] = a1.y;
        As[(k4 * 4 + 2) * SA + m0 + 64] = a1.z;
        As[(k4 * 4 + 3) * SA + m0 + 64] = a1.w;
        Bs[(k4 * 4 + 0) * SA + m0] = b0.x;
        Bs[(k4 * 4 + 1) * SA + m0] = b0.y;
        Bs[(k4 * 4 + 2) * SA + m0] = b0.z;
        Bs[(k4 * 4 + 3) * SA + m0] = b0.w;
        Bs[(k4 * 4 + 0) * SA + m0 + 64] = b1.x;
        Bs[(k4 * 4 + 1) * SA + m0 + 64] = b1.y;
        Bs[(k4 * 4 + 2) * SA + m0 + 64] = b1.z;
        Bs[(k4 * 4 + 3) * SA + m0 + 64] = b1.w;
        __syncthreads();

#pragma unroll
        for (int kk = 0; kk < 16; ++kk) {
            float4 av0 = *(const float4*)&As[kk * SA + ty * 8];
            float4 av1 = *(const float4*)&As[kk * SA + ty * 8 + 4];
            ulonglong2 bu0 = *(const ulonglong2*)&Bs[kk * SA + tx * 8];
            ulonglong2 bu1 = *(const ulonglong2*)&Bs[kk * SA + tx * 8 + 4];
            const ull bq0 = bu0.x, bq1 = bu0.y, bq2 = bu1.x, bq3 = bu1.y;
            float av[8] = {av0.x, av0.y, av0.z, av0.w,
                           av1.x, av1.y, av1.z, av1.w};
#pragma unroll
            for (int i = 0; i < 8; ++i) {
                ull ad = pk2(av[i]);
                FMA2(acc[i][0], ad, bq0);
                FMA2(acc[i][1], ad, bq1);
                FMA2(acc[i][2], ad, bq2);
                FMA2(acc[i][3], ad, bq3);
            }
        }
    }

#pragma unroll
    for (int i = 0; i < 8; ++i) {
        const int row = bm * 128 + ty * 8 + i;
        float* crow = C + (size_t)row * N;
#pragma unroll
        for (int j = 0; j < 4; ++j) {
            const int col = bn * 128 + tx * 8 + 2 * j;
            if (col < N) {
                float lo, hi;
                unpk(lo, hi, acc[i][j]);
                lo += bias[col];
                hi += bias[col + 1];
                *(float2*)(crow + col) = make_float2(lo, hi);
            }
        }
    }
}

// ---------------------------------------------------------------------------
// Persistent LSTM layer. f32x2 dot; flag-array barrier (release/acquire,
// one flag per (t, cta) — no atomics, no hot line).
// ---------------------------------------------------------------------------
#define WPAD 33
#define LSTM_SMEM_FLOATS (1024 * WPAD + 1024 * 4 + 256 * 4 + 128)
#define LSTM_SMEM_BYTES (LSTM_SMEM_FLOATS * 4)

__global__ __launch_bounds__(256) void lstm_layer(
    const float* __restrict__ xg,
    const float* __restrict__ Whh,
    float* __restrict__ hseq,
    float* __restrict__ hT)
{
    extern __shared__ float sm[];
    float*  Wsm  = sm;
    float4* hsm  = (float4*)(sm + 1024 * WPAD);
    float*  red  = (float*)(hsm + 1024);
    float*  gbuf = red + 1024;

    const int tid = threadIdx.x;
    const int cta = blockIdx.x;

    for (int i = tid; i < 32 * 1024; i += 256) {
        const int r = i >> 10, k = i & 1023;
        const int grow = (r >> 3) * HH + cta * 8 + (r & 7);
        Wsm[k * WPAD + r] = Whh[(size_t)grow * HH + k];
    }
    for (int i = tid; i < 1024; i += 256)
        hsm[i] = make_float4(0.f, 0.f, 0.f, 0.f);
    __syncthreads();

    const int row32 = tid & 31, kseg = tid >> 5;
    const int rrow = tid >> 2, rb = tid & 3;
    float cstate = 0.f;

    for (int t = 0; t < TT; ++t) {
        float xval = 0.f;
        if (tid < 128) {
            const int grow = (rrow >> 3) * HH + cta * 8 + (rrow & 7);
            xval = __ldg(&xg[((size_t)(rb * TT + t)) * GG + grow]);
        }

        // f32x2 dot: 32 gate-rows x 4 batches over 8 k-segments
        ull acc0 = 0ull, acc1 = 0ull;
        const float*      wp = &Wsm[(kseg * 128) * WPAD + row32];
        const ulonglong2* hp = (const ulonglong2*)&hsm[kseg * 128];
#pragma unroll 8
        for (int k = 0; k < 128; ++k) {
            const ull        wd = pk2(wp[k * WPAD]);
            const ulonglong2 h2 = hp[k];
            FMA2(acc0, wd, h2.x);
            FMA2(acc1, wd, h2.y);
        }
        float4 p;
        unpk(p.x, p.y, acc0);
        unpk(p.z, p.w, acc1);
        ((float4*)red)[tid] = p;
        __syncthreads();

        if (tid < 128) {
            float s = xval;
#pragma unroll
            for (int sg = 0; sg < 8; ++sg)
                s += red[sg * 128 + tid];
            gbuf[tid] = s;
        }
        __syncthreads();

        if (tid < 32) {
            const int gu = tid >> 2, gb = tid & 3;
            float gi = gbuf[(0 * 8 + gu) * 4 + gb];
            float gf = gbuf[(1 * 8 + gu) * 4 + gb];
            float gg = gbuf[(2 * 8 + gu) * 4 + gb];
            float go = gbuf[(3 * 8 + gu) * 4 + gb];
            gi = 1.f / (1.f + __expf(-gi));
            gf = 1.f / (1.f + __expf(-gf));
            gg = tanhf(gg);
            go = 1.f / (1.f + __expf(-go));
            cstate = gf * cstate + gi * gg;
            const float h = go * tanhf(cstate);
            const int unit = cta * 8 + gu;
            hseq[((size_t)(gb * TT + t)) * HH + unit] = h;
            __stcg(&hT[(t & 1) * (HH * 4) + unit * 4 + gb], h);
        }
        __syncthreads();

        // barrier: release-store own flag, acquire-poll all 128 flags
        if (tid == 0) {
            asm volatile("st.release.gpu.global.u32 [%0], %1;"
                         :: "l"(&g_flags[t * NCTA + cta]), "r"(1u) : "memory");
        }
        if (tid < NCTA) {
            const unsigned* fp = &g_flags[t * NCTA + tid];
            unsigned v;
            do {
                asm volatile("ld.acquire.gpu.global.u32 %0, [%1];"
                             : "=r"(v) : "l"(fp) : "memory");
            } while (v == 0u);
        }
        __syncthreads();

        const float4* src = (const float4*)&hT[(t & 1) * (HH * 4)];
        for (int i = tid; i < 1024; i += 256)
            hsm[i] = __ldcg(src + i);
        __syncthreads();
    }
}

// ---------------------------------------------------------------------------
// log-softmax
// ---------------------------------------------------------------------------
__global__ __launch_bounds__(256) void rowstats(
    const float* __restrict__ logits, float* __restrict__ lse)
{
    const int row = blockIdx.x, tid = threadIdx.x;
    const float4* p = (const float4*)(logits + (size_t)row * VV);
    float m = -1e30f, s = 0.f;
    for (int i = tid; i < VV / 4; i += 256) {
        const float4 v = p[i];
        const float vm = fmaxf(fmaxf(v.x, v.y), fmaxf(v.z, v.w));
        if (vm > m) { s *= __expf(m - vm); m = vm; }
        s += __expf(v.x - m) + __expf(v.y - m) +
             __expf(v.z - m) + __expf(v.w - m);
    }
    __shared__ float sm_m[256], sm_s[256];
    sm_m[tid] = m; sm_s[tid] = s;
    __syncthreads();
    for (int off = 128; off > 0; off >>= 1) {
        if (tid < off) {
            const float m2 = sm_m[tid + off], s2 = sm_s[tid + off];
            const float mm = fmaxf(sm_m[tid], m2);
            sm_s[tid] = sm_s[tid] * __expf(sm_m[tid] - mm) + s2 * __expf(m2 - mm);
            sm_m[tid] = mm;
        }
        __syncthreads();
    }
    if (tid == 0) lse[row] = sm_m[0] + __logf(sm_s[0]);
}

__global__ __launch_bounds__(256) void finalize_ls(
    float* __restrict__ out, const float* __restrict__ lse)
{
    const size_t i = (size_t)blockIdx.x * 256 + threadIdx.x;
    const size_t total = (size_t)BT * VV / 4;
    if (i < total) {
        const int row = (int)((i * 4) / VV);
        const float l = lse[row];
        float4 v = ((float4*)out)[i];
        v.x -= l; v.y -= l; v.z -= l; v.w -= l;
        ((float4*)out)[i] = v;
    }
}

// ---------------------------------------------------------------------------
extern "C" void kernel_launch(void* const* d_in, const int* in_sizes, int n_in,
                              void* d_out, int out_size)
{
    const int*   token_idx = (const int*)  d_in[0];
    const float* X         = (const float*)d_in[1];
    const float* W_ih0     = (const float*)d_in[2];
    const float* W_hh0     = (const float*)d_in[3];
    const float* b0        = (const float*)d_in[4];
    const float* W_ih1     = (const float*)d_in[5];
    const float* W_hh1     = (const float*)d_in[6];
    const float* b1        = (const float*)d_in[7];
    const float* W_out     = (const float*)d_in[8];
    const float* b_out     = (const float*)d_in[9];
    float* out = (float*)d_out;

    float* xg = nullptr;  cudaGetSymbolAddress((void**)&xg, g_xg);
    float* h0 = nullptr;  cudaGetSymbolAddress((void**)&h0, g_h0);
    float* h1 = nullptr;  cudaGetSymbolAddress((void**)&h1, g_h1);
    float* hT = nullptr;  cudaGetSymbolAddress((void**)&hT, g_hT);
    float* lse = nullptr; cudaGetSymbolAddress((void**)&lse, g_lse);
    __nv_bfloat16* wb = nullptr; cudaGetSymbolAddress((void**)&wb, g_wb);
    __nv_bfloat16* hb = nullptr; cudaGetSymbolAddress((void**)&hb, g_hb);

    cudaFuncSetAttribute(lstm_layer,
        cudaFuncAttributeMaxDynamicSharedMemorySize, LSTM_SMEM_BYTES);
    cudaFuncSetAttribute(gemm_mma,
        cudaFuncAttributeMaxDynamicSharedMemorySize, MMA_SMEM);

    // W_out f32 -> bf16 (padded rows zero-filled)
    {
        const size_t nsrc = (size_t)VV * HH, ntot = (size_t)VPAD * HH;
        conv_bf16<<<(unsigned)((ntot / 4 + 255) / 256), 256>>>(W_out, wb, nsrc, ntot);
    }

    // K1: xg0 = emb @ W_ih0^T + b0
    gemm_tn<<<dim3(GG / 128, BT / 128), 256>>>(
        nullptr, W_ih0, b0, xg, BT, GG, DD, token_idx, X);

    zero_flags<<<TT * NCTA / 256, 256>>>();
    lstm_layer<<<NCTA, 256, LSTM_SMEM_BYTES>>>(xg, W_hh0, h0, hT);

    // K3: xg1 = h0 @ W_ih1^T + b1
    gemm_tn<<<dim3(GG / 128, BT / 128), 256>>>(
        h0, W_ih1, b1, xg, BT, GG, HH, nullptr, nullptr);

    zero_flags<<<TT * NCTA / 256, 256>>>();
    lstm_layer<<<NCTA, 256, LSTM_SMEM_BYTES>>>(xg, W_hh1, h1, hT);

    // h1 f32 -> bf16
    {
        const size_t n = (size_t)BT * HH;
        conv_bf16<<<(unsigned)((n / 4 + 255) / 256), 256>>>(h1, hb, n, n);
    }

    // K5: logits = h1 @ W_out^T + b_out (HMMA, cp.async double-buffered)
    gemm_mma<<<dim3(BT / 128, VPAD / 128), 256, MMA_SMEM>>>(hb, wb, b_out, out);

    rowstats<<<BT, 256>>>(out, lse);
    const size_t total4 = (size_t)BT * VV / 4;
    finalize_ls<<<(unsigned)((total4 + 255) / 256), 256>>>(out, lse);
}

// round 13
// speedup vs baseline: 2.1212x; 2.1212x over previous
#include <cuda_runtime.h>
#include <cuda_bf16.h>
#include <cstdint>
#include <cstddef>
#include <math.h>

#define BQ 4
#define TT 512
#define BT (BQ * TT)      // 2048
#define DD 512
#define HH 1024
#define GG (4 * HH)       // 4096
#define VV 50000
#define VPAD 50048        // 391 * 128
#define NCTA 128          // persistent LSTM CTAs

using ull = unsigned long long;

// ---------------- packed f32x2 helpers ----------------
__device__ __forceinline__ ull pk2(float v) {
    ull r; asm("mov.b64 %0, {%1,%2};" : "=l"(r) : "f"(v), "f"(v)); return r;
}
__device__ __forceinline__ void unpk(float& lo, float& hi, ull v) {
    asm("mov.b64 {%0,%1}, %2;" : "=f"(lo), "=f"(hi) : "l"(v));
}
#define FMA2(acc, a, b) \
    asm("fma.rn.f32x2 %0, %1, %2, %0;" : "+l"(acc) : "l"(a), "l"(b))

// ---------------- device scratch ----------------
__device__ float g_xg[(size_t)BT * GG];
__device__ float g_h0[(size_t)BT * HH];
__device__ float g_h1[(size_t)BT * HH];
__device__ float g_hT[2 * HH * BQ];
__device__ float g_lse[BT];
__device__ unsigned g_cnt;
__device__ __nv_bfloat16 g_wb[(size_t)VPAD * HH];   // bf16 W_out, padded
__device__ __nv_bfloat16 g_hb[(size_t)BT * HH];     // bf16 h1

__global__ void reset_bar() { g_cnt = 0u; }

// ---------------------------------------------------------------------------
// f32 -> bf16 conversion (zero-pads tail rows for W)
// ---------------------------------------------------------------------------
__global__ __launch_bounds__(256) void conv_bf16(
    const float* __restrict__ src, __nv_bfloat16* __restrict__ dst,
    size_t n_src, size_t n_total)
{
    const size_t i = ((size_t)blockIdx.x * 256 + threadIdx.x) * 4;
    if (i >= n_total) return;
    uint2 o;
    if (i < n_src) {
        const float4 v = *(const float4*)(src + i);
        __nv_bfloat162 lo = __floats2bfloat162_rn(v.x, v.y);
        __nv_bfloat162 hi = __floats2bfloat162_rn(v.z, v.w);
        o.x = *(unsigned*)&lo;
        o.y = *(unsigned*)&hi;
    } else {
        o.x = 0u; o.y = 0u;
    }
    *(uint2*)(dst + i) = o;
}

// ---------------------------------------------------------------------------
// mma.sync bf16 GEMM with cp.async double buffering (R10 WIN — unchanged)
// ---------------------------------------------------------------------------
__device__ __forceinline__ uint32_t smem_u32(const void* p) {
    uint32_t a;
    asm("{ .reg .u64 t; cvta.to.shared.u64 t, %1; cvt.u32.u64 %0, t; }"
        : "=r"(a) : "l"(p));
    return a;
}
#define LDSM_X4(r0, r1, r2, r3, addr) \
    asm volatile("ldmatrix.sync.aligned.m8n8.x4.shared.b16 {%0,%1,%2,%3}, [%4];" \
        : "=r"(r0), "=r"(r1), "=r"(r2), "=r"(r3) : "r"(addr))
#define MMA16816(c, a0, a1, a2, a3, b0, b1) \
    asm volatile("mma.sync.aligned.m16n8k16.row.col.f32.bf16.bf16.f32 " \
        "{%0,%1,%2,%3}, {%4,%5,%6,%7}, {%8,%9}, {%0,%1,%2,%3};" \
        : "+f"((c)[0]), "+f"((c)[1]), "+f"((c)[2]), "+f"((c)[3]) \
        : "r"(a0), "r"(a1), "r"(a2), "r"(a3), "r"(b0), "r"(b1))
#define CP16(saddr, gptr) \
    asm volatile("cp.async.cg.shared.global [%0], [%1], 16;" \
        :: "r"(saddr), "l"(gptr))

#define MMA_SMEM 65536   // 2 bufs x (16KB A + 16KB B)

__global__ __launch_bounds__(256, 2) void gemm_mma(
    const __nv_bfloat16* __restrict__ A,   // [2048][1024]
    const __nv_bfloat16* __restrict__ B,   // [50048][1024]
    const float* __restrict__ bias, float* __restrict__ C)
{
    extern __shared__ __align__(16) char smem_mma[];
    const uint32_t smb = smem_u32(smem_mma);

    const int tid = threadIdx.x;
    const int bm = blockIdx.x, bn = blockIdx.y;
    const int lane = tid & 31, wid = tid >> 5;
    const int wm = wid & 3, wn = wid >> 2;
    const int g = lane >> 3, l8 = lane & 7;

    float acc[2][8][4];
#pragma unroll
    for (int mt = 0; mt < 2; ++mt)
#pragma unroll
        for (int nt = 0; nt < 8; ++nt)
#pragma unroll
            for (int q = 0; q < 4; ++q) acc[mt][nt][q] = 0.f;

    const int arow0 = wm * 32 + (g & 1) * 8 + l8;
    const int aug   = g >> 1;
    const int brow0 = wn * 64 + (g >> 1) * 8 + l8;
    const int bug   = g & 1;

    const int lrow = tid >> 3, lunit = tid & 7;
    const __nv_bfloat16* Abase = A + (size_t)(bm * 128) * HH;
    const __nv_bfloat16* Bbase = B + (size_t)(bn * 128) * HH;

    int rowv[4];
    uint32_t soff[4];
#pragma unroll
    for (int i = 0; i < 4; ++i) {
        rowv[i] = lrow + i * 32;
        soff[i] = (uint32_t)rowv[i] * 128u
                + ((uint32_t)(lunit ^ (rowv[i] & 7)) << 4);
    }

    auto issue_chunk = [&](int kc, int buf) {
        const uint32_t ab = smb + (uint32_t)buf * 32768u;
        const uint32_t bb = ab + 16384u;
#pragma unroll
        for (int i = 0; i < 4; ++i) {
            CP16(ab + soff[i],
                 Abase + (size_t)rowv[i] * HH + kc * 64 + lunit * 8);
            CP16(bb + soff[i],
                 Bbase + (size_t)rowv[i] * HH + kc * 64 + lunit * 8);
        }
    };

    issue_chunk(0, 0);
    asm volatile("cp.async.commit_group;" ::: "memory");

    for (int kc = 0; kc < HH / 64; ++kc) {
        const int buf = kc & 1;
        if (kc + 1 < HH / 64) {
            issue_chunk(kc + 1, buf ^ 1);
            asm volatile("cp.async.commit_group;" ::: "memory");
            asm volatile("cp.async.wait_group 1;" ::: "memory");
        } else {
            asm volatile("cp.async.wait_group 0;" ::: "memory");
        }
        __syncthreads();

        const uint32_t asmb = smb + (uint32_t)buf * 32768u;
        const uint32_t bsmb = asmb + 16384u;
#pragma unroll
        for (int ks = 0; ks < 4; ++ks) {
            uint32_t a[2][4];
#pragma unroll
            for (int mt = 0; mt < 2; ++mt) {
                const int row = arow0 + mt * 16;
                const uint32_t addr = asmb + (uint32_t)row * 128u
                    + ((uint32_t)((ks * 2 + aug) ^ l8) << 4);
                LDSM_X4(a[mt][0], a[mt][1], a[mt][2], a[mt][3], addr);
            }
#pragma unroll
            for (int p = 0; p < 4; ++p) {
                const int row = brow0 + p * 16;
                const uint32_t addr = bsmb + (uint32_t)row * 128u
                    + ((uint32_t)((ks * 2 + bug) ^ l8) << 4);
                uint32_t b0, b1, b2, b3;
                LDSM_X4(b0, b1, b2, b3, addr);
                MMA16816(acc[0][2 * p],     a[0][0], a[0][1], a[0][2], a[0][3], b0, b1);
                MMA16816(acc[0][2 * p + 1], a[0][0], a[0][1], a[0][2], a[0][3], b2, b3);
                MMA16816(acc[1][2 * p],     a[1][0], a[1][1], a[1][2], a[1][3], b0, b1);
                MMA16816(acc[1][2 * p + 1], a[1][0], a[1][1], a[1][2], a[1][3], b2, b3);
            }
        }
        __syncthreads();
    }

    const int mrow = lane >> 2, nc2 = (lane & 3) * 2;
#pragma unroll
    for (int mt = 0; mt < 2; ++mt) {
        const int row0 = bm * 128 + wm * 32 + mt * 16 + mrow;
        float* c0 = C + (size_t)row0 * VV;
        float* c1 = C + (size_t)(row0 + 8) * VV;
#pragma unroll
        for (int nt = 0; nt < 8; ++nt) {
            const int col = bn * 128 + wn * 64 + nt * 8 + nc2;
            if (col < VV) {
                const float bx = __ldg(bias + col);
                const float by = __ldg(bias + col + 1);
                *(float2*)(c0 + col) =
                    make_float2(acc[mt][nt][0] + bx, acc[mt][nt][1] + by);
                *(float2*)(c1 + col) =
                    make_float2(acc[mt][nt][2] + bx, acc[mt][nt][3] + by);
            }
        }
    }
}

// ---------------------------------------------------------------------------
// SIMT f32x2 GEMM (K1/K3) — unchanged
// ---------------------------------------------------------------------------
#define SA 132

__global__ __launch_bounds__(256) void gemm_tn(
    const float* __restrict__ A, const float* __restrict__ B,
    const float* __restrict__ bias, float* __restrict__ C,
    int M, int N, int K,
    const int* __restrict__ gatherIdx, const float* __restrict__ Xsrc)
{
    __shared__ __align__(16) float As[16 * SA];
    __shared__ __align__(16) float Bs[16 * SA];

    const int tid = threadIdx.x;
    const int bn = blockIdx.x, bm = blockIdx.y;
    const int tx = tid & 15, ty = tid >> 4;

    ull acc[8][4];
#pragma unroll
    for (int i = 0; i < 8; ++i)
#pragma unroll
        for (int j = 0; j < 4; ++j) acc[i][j] = 0ull;

    const int m0 = tid >> 2;
    const int k4 = tid & 3;

    const int gm0 = bm * 128 + m0;
    const int gm1 = gm0 + 64;
    const float* arow0;
    const float* arow1;
    if (gatherIdx) {
        arow0 = Xsrc + (size_t)gatherIdx[gm0] * K;
        arow1 = Xsrc + (size_t)gatherIdx[gm1] * K;
    } else {
        arow0 = A + (size_t)gm0 * K;
        arow1 = A + (size_t)gm1 * K;
    }
    const int gn0 = bn * 128 + m0;
    const int gn1 = gn0 + 64;
    const bool bv0 = gn0 < N, bv1 = gn1 < N;
    const float* brow0 = B + (size_t)gn0 * K;
    const float* brow1 = B + (size_t)gn1 * K;
    const float4 z4 = make_float4(0.f, 0.f, 0.f, 0.f);

    for (int kt = 0; kt < K; kt += 16) {
        float4 a0 = *(const float4*)(arow0 + kt + k4 * 4);
        float4 a1 = *(const float4*)(arow1 + kt + k4 * 4);
        float4 b0 = bv0 ? *(const float4*)(brow0 + kt + k4 * 4) : z4;
        float4 b1 = bv1 ? *(const float4*)(brow1 + kt + k4 * 4) : z4;

        __syncthreads();
        As[(k4 * 4 + 0) * SA + m0] = a0.x;
        As[(k4 * 4 + 1) * SA + m0] = a0.y;
        As[(k4 * 4 + 2) * SA + m0] = a0.z;
        As[(k4 * 4 + 3) * SA + m0] = a0.w;
        As[(k4 * 4 + 0) * SA + m0 + 64] = a1.x;
        As[(k4 * 4 + 1) * SA + m0 + 64] = a1.y;
        As[(k4 * 4 + 2) * SA + m0 + 64] = a1.z;
        As[(k4 * 4 + 3) * SA + m0 + 64] = a1.w;
        Bs[(k4 * 4 + 0) * SA + m0] = b0.x;
        Bs[(k4 * 4 + 1) * SA + m0] = b0.y;
        Bs[(k4 * 4 + 2) * SA + m0] = b0.z;
        Bs[(k4 * 4 + 3) * SA + m0] = b0.w;
        Bs[(k4 * 4 + 0) * SA + m0 + 64] = b1.x;
        Bs[(k4 * 4 + 1) * SA + m0 + 64] = b1.y;
        Bs[(k4 * 4 + 2) * SA + m0 + 64] = b1.z;
        Bs[(k4 * 4 + 3) * SA + m0 + 64] = b1.w;
        __syncthreads();

#pragma unroll
        for (int kk = 0; kk < 16; ++kk) {
            float4 av0 = *(const float4*)&As[kk * SA + ty * 8];
            float4 av1 = *(const float4*)&As[kk * SA + ty * 8 + 4];
            ulonglong2 bu0 = *(const ulonglong2*)&Bs[kk * SA + tx * 8];
            ulonglong2 bu1 = *(const ulonglong2*)&Bs[kk * SA + tx * 8 + 4];
            const ull bq0 = bu0.x, bq1 = bu0.y, bq2 = bu1.x, bq3 = bu1.y;
            float av[8] = {av0.x, av0.y, av0.z, av0.w,
                           av1.x, av1.y, av1.z, av1.w};
#pragma unroll
            for (int i = 0; i < 8; ++i) {
                ull ad = pk2(av[i]);
                FMA2(acc[i][0], ad, bq0);
                FMA2(acc[i][1], ad, bq1);
                FMA2(acc[i][2], ad, bq2);
                FMA2(acc[i][3], ad, bq3);
            }
        }
    }

#pragma unroll
    for (int i = 0; i < 8; ++i) {
        const int row = bm * 128 + ty * 8 + i;
        float* crow = C + (size_t)row * N;
#pragma unroll
        for (int j = 0; j < 4; ++j) {
            const int col = bn * 128 + tx * 8 + 2 * j;
            if (col < N) {
                float lo, hi;
                unpk(lo, hi, acc[i][j]);
                lo += bias[col];
                hi += bias[col + 1];
                *(float2*)(crow + col) = make_float2(lo, hi);
            }
        }
    }
}

// ---------------------------------------------------------------------------
// Persistent LSTM layer. R10 barrier (atomic arrival + tid0 relaxed poll —
// proven) + f32x2 dot (halves the FMA issue floor).
// ---------------------------------------------------------------------------
#define WPAD 33
#define LSTM_SMEM_FLOATS (1024 * WPAD + 1024 * 4 + 256 * 4 + 128)
#define LSTM_SMEM_BYTES (LSTM_SMEM_FLOATS * 4)

__global__ __launch_bounds__(256) void lstm_layer(
    const float* __restrict__ xg,
    const float* __restrict__ Whh,
    float* __restrict__ hseq,
    float* __restrict__ hT)
{
    extern __shared__ float sm[];
    float*  Wsm  = sm;
    float4* hsm  = (float4*)(sm + 1024 * WPAD);
    float*  red  = (float*)(hsm + 1024);
    float*  gbuf = red + 1024;

    const int tid = threadIdx.x;
    const int cta = blockIdx.x;

    for (int i = tid; i < 32 * 1024; i += 256) {
        const int r = i >> 10, k = i & 1023;
        const int grow = (r >> 3) * HH + cta * 8 + (r & 7);
        Wsm[k * WPAD + r] = Whh[(size_t)grow * HH + k];
    }
    for (int i = tid; i < 1024; i += 256)
        hsm[i] = make_float4(0.f, 0.f, 0.f, 0.f);
    __syncthreads();

    const int row32 = tid & 31, kseg = tid >> 5;
    const int rrow = tid >> 2, rb = tid & 3;
    float cstate = 0.f;

    for (int t = 0; t < TT; ++t) {
        float xval = 0.f;
        if (tid < 128) {
            const int grow = (rrow >> 3) * HH + cta * 8 + (rrow & 7);
            xval = __ldg(&xg[((size_t)(rb * TT + t)) * GG + grow]);
        }

        // f32x2 dot: 32 gate-rows x 4 batches over 8 k-segments
        ull acc0 = 0ull, acc1 = 0ull;
        const float*      wp = &Wsm[(kseg * 128) * WPAD + row32];
        const ulonglong2* hp = (const ulonglong2*)&hsm[kseg * 128];
#pragma unroll 8
        for (int k = 0; k < 128; ++k) {
            const ull        wd = pk2(wp[k * WPAD]);
            const ulonglong2 h2 = hp[k];
            FMA2(acc0, wd, h2.x);
            FMA2(acc1, wd, h2.y);
        }
        float4 p;
        unpk(p.x, p.y, acc0);
        unpk(p.z, p.w, acc1);
        ((float4*)red)[tid] = p;
        __syncthreads();

        if (tid < 128) {
            float s = xval;
#pragma unroll
            for (int sg = 0; sg < 8; ++sg)
                s += red[sg * 128 + tid];
            gbuf[tid] = s;
        }
        __syncthreads();

        if (tid < 32) {
            const int gu = tid >> 2, gb = tid & 3;
            float gi = gbuf[(0 * 8 + gu) * 4 + gb];
            float gf = gbuf[(1 * 8 + gu) * 4 + gb];
            float gg = gbuf[(2 * 8 + gu) * 4 + gb];
            float go = gbuf[(3 * 8 + gu) * 4 + gb];
            gi = 1.f / (1.f + __expf(-gi));
            gf = 1.f / (1.f + __expf(-gf));
            gg = tanhf(gg);
            go = 1.f / (1.f + __expf(-go));
            cstate = gf * cstate + gi * gg;
            const float h = go * tanhf(cstate);
            const int unit = cta * 8 + gu;
            hseq[((size_t)(gb * TT + t)) * HH + unit] = h;
            __stcg(&hT[(t & 1) * (HH * 4) + unit * 4 + gb], h);
        }

        // grid barrier: atomic arrival, single-thread relaxed L2 poll (R10)
        __threadfence();
        __syncthreads();
        if (tid == 0) {
            atomicAdd(&g_cnt, 1u);
            const unsigned target = (unsigned)NCTA * (unsigned)(t + 1);
            unsigned v;
            do {
                asm volatile("ld.global.cg.u32 %0, [%1];"
                             : "=r"(v) : "l"(&g_cnt));
            } while (v < target);
        }
        __syncthreads();

        const float4* src = (const float4*)&hT[(t & 1) * (HH * 4)];
        for (int i = tid; i < 1024; i += 256)
            hsm[i] = __ldcg(src + i);
        __syncthreads();
    }
}

// ---------------------------------------------------------------------------
// log-softmax
// ---------------------------------------------------------------------------
__global__ __launch_bounds__(256) void rowstats(
    const float* __restrict__ logits, float* __restrict__ lse)
{
    const int row = blockIdx.x, tid = threadIdx.x;
    const float4* p = (const float4*)(logits + (size_t)row * VV);
    float m = -1e30f, s = 0.f;
    for (int i = tid; i < VV / 4; i += 256) {
        const float4 v = p[i];
        const float vm = fmaxf(fmaxf(v.x, v.y), fmaxf(v.z, v.w));
        if (vm > m) { s *= __expf(m - vm); m = vm; }
        s += __expf(v.x - m) + __expf(v.y - m) +
             __expf(v.z - m) + __expf(v.w - m);
    }
    __shared__ float sm_m[256], sm_s[256];
    sm_m[tid] = m; sm_s[tid] = s;
    __syncthreads();
    for (int off = 128; off > 0; off >>= 1) {
        if (tid < off) {
            const float m2 = sm_m[tid + off], s2 = sm_s[tid + off];
            const float mm = fmaxf(sm_m[tid], m2);
            sm_s[tid] = sm_s[tid] * __expf(sm_m[tid] - mm) + s2 * __expf(m2 - mm);
            sm_m[tid] = mm;
        }
        __syncthreads();
    }
    if (tid == 0) lse[row] = sm_m[0] + __logf(sm_s[0]);
}

__global__ __launch_bounds__(256) void finalize_ls(
    float* __restrict__ out, const float* __restrict__ lse)
{
    const size_t i = (size_t)blockIdx.x * 256 + threadIdx.x;
    const size_t total = (size_t)BT * VV / 4;
    if (i < total) {
        const int row = (int)((i * 4) / VV);
        const float l = lse[row];
        float4 v = ((float4*)out)[i];
        v.x -= l; v.y -= l; v.z -= l; v.w -= l;
        ((float4*)out)[i] = v;
    }
}

// ---------------------------------------------------------------------------
extern "C" void kernel_launch(void* const* d_in, const int* in_sizes, int n_in,
                              void* d_out, int out_size)
{
    const int*   token_idx = (const int*)  d_in[0];
    const float* X         = (const float*)d_in[1];
    const float* W_ih0     = (const float*)d_in[2];
    const float* W_hh0     = (const float*)d_in[3];
    const float* b0        = (const float*)d_in[4];
    const float* W_ih1     = (const float*)d_in[5];
    const float* W_hh1     = (const float*)d_in[6];
    const float* b1        = (const float*)d_in[7];
    const float* W_out     = (const float*)d_in[8];
    const float* b_out     = (const float*)d_in[9];
    float* out = (float*)d_out;

    float* xg = nullptr;  cudaGetSymbolAddress((void**)&xg, g_xg);
    float* h0 = nullptr;  cudaGetSymbolAddress((void**)&h0, g_h0);
    float* h1 = nullptr;  cudaGetSymbolAddress((void**)&h1, g_h1);
    float* hT = nullptr;  cudaGetSymbolAddress((void**)&hT, g_hT);
    float* lse = nullptr; cudaGetSymbolAddress((void**)&lse, g_lse);
    __nv_bfloat16* wb = nullptr; cudaGetSymbolAddress((void**)&wb, g_wb);
    __nv_bfloat16* hb = nullptr; cudaGetSymbolAddress((void**)&hb, g_hb);

    cudaFuncSetAttribute(lstm_layer,
        cudaFuncAttributeMaxDynamicSharedMemorySize, LSTM_SMEM_BYTES);
    cudaFuncSetAttribute(gemm_mma,
        cudaFuncAttributeMaxDynamicSharedMemorySize, MMA_SMEM);

    // W_out f32 -> bf16 (padded rows zero-filled)
    {
        const size_t nsrc = (size_t)VV * HH, ntot = (size_t)VPAD * HH;
        conv_bf16<<<(unsigned)((ntot / 4 + 255) / 256), 256>>>(W_out, wb, nsrc, ntot);
    }

    // K1: xg0 = emb @ W_ih0^T + b0
    gemm_tn<<<dim3(GG / 128, BT / 128), 256>>>(
        nullptr, W_ih0, b0, xg, BT, GG, DD, token_idx, X);

    reset_bar<<<1, 1>>>();
    lstm_layer<<<NCTA, 256, LSTM_SMEM_BYTES>>>(xg, W_hh0, h0, hT);

    // K3: xg1 = h0 @ W_ih1^T + b1
    gemm_tn<<<dim3(GG / 128, BT / 128), 256>>>(
        h0, W_ih1, b1, xg, BT, GG, HH, nullptr, nullptr);

    reset_bar<<<1, 1>>>();
    lstm_layer<<<NCTA, 256, LSTM_SMEM_BYTES>>>(xg, W_hh1, h1, hT);

    // h1 f32 -> bf16
    {
        const size_t n = (size_t)BT * HH;
        conv_bf16<<<(unsigned)((n / 4 + 255) / 256), 256>>>(h1, hb, n, n);
    }

    // K5: logits = h1 @ W_out^T + b_out (HMMA, cp.async double-buffered)
    gemm_mma<<<dim3(BT / 128, VPAD / 128), 256, MMA_SMEM>>>(hb, wb, b_out, out);

    rowstats<<<BT, 256>>>(out, lse);
    const size_t total4 = (size_t)BT * VV / 4;
    finalize_ls<<<(unsigned)((total4 + 255) / 256), 256>>>(out, lse);
}

// round 14
// speedup vs baseline: 2.4891x; 1.1734x over previous
#include <cuda_runtime.h>
#include <cuda_bf16.h>
#include <cstdint>
#include <cstddef>
#include <math.h>

#define BQ 4
#define TT 512
#define BT (BQ * TT)      // 2048
#define DD 512
#define HH 1024
#define GG (4 * HH)       // 4096
#define VV 50000
#define VPAD 50048        // 391 * 128
#define NCTA 128          // persistent LSTM CTAs

using ull = unsigned long long;

// ---------------- device scratch ----------------
__device__ float g_xg[(size_t)BT * GG];
__device__ float g_h0[(size_t)BT * HH];
__device__ float g_h1[(size_t)BT * HH];
__device__ float g_hT[2 * HH * BQ];
__device__ float g_lse[BT];
__device__ unsigned g_cnt;
__device__ __nv_bfloat16 g_wb[(size_t)VPAD * HH];    // bf16 W_out (padded)
__device__ __nv_bfloat16 g_hb[(size_t)BT * HH];      // bf16 h1
__device__ __nv_bfloat16 g_h0b[(size_t)BT * HH];     // bf16 h0
__device__ __nv_bfloat16 g_wi0b[(size_t)GG * DD];    // bf16 W_ih0
__device__ __nv_bfloat16 g_wi1b[(size_t)GG * HH];    // bf16 W_ih1
__device__ __nv_bfloat16 g_embB[(size_t)BT * DD];    // bf16 gathered emb

__global__ void reset_bar() { g_cnt = 0u; }

// ---------------------------------------------------------------------------
// f32 -> bf16 conversion (zero-pads tail for W_out)
// ---------------------------------------------------------------------------
__global__ __launch_bounds__(256) void conv_bf16(
    const float* __restrict__ src, __nv_bfloat16* __restrict__ dst,
    size_t n_src, size_t n_total)
{
    const size_t i = ((size_t)blockIdx.x * 256 + threadIdx.x) * 4;
    if (i >= n_total) return;
    uint2 o;
    if (i < n_src) {
        const float4 v = *(const float4*)(src + i);
        __nv_bfloat162 lo = __floats2bfloat162_rn(v.x, v.y);
        __nv_bfloat162 hi = __floats2bfloat162_rn(v.z, v.w);
        o.x = *(unsigned*)&lo;
        o.y = *(unsigned*)&hi;
    } else {
        o.x = 0u; o.y = 0u;
    }
    *(uint2*)(dst + i) = o;
}

// gather token embeddings and convert to bf16: dst[r][c] = X[tok[r]][c]
__global__ __launch_bounds__(256) void gather_emb(
    const int* __restrict__ tok, const float* __restrict__ X,
    __nv_bfloat16* __restrict__ dst)
{
    const size_t i = ((size_t)blockIdx.x * 256 + threadIdx.x) * 4;
    if (i >= (size_t)BT * DD) return;
    const int row = (int)(i >> 9);         // DD=512
    const int col = (int)(i & (DD - 1));
    const float4 v = *(const float4*)(X + (size_t)tok[row] * DD + col);
    __nv_bfloat162 lo = __floats2bfloat162_rn(v.x, v.y);
    __nv_bfloat162 hi = __floats2bfloat162_rn(v.z, v.w);
    uint2 o;
    o.x = *(unsigned*)&lo;
    o.y = *(unsigned*)&hi;
    *(uint2*)(dst + i) = o;
}

// ---------------------------------------------------------------------------
// mma.sync bf16 GEMM (generalized): C[M, ldc] = A[M,K].B[Npad,K]^T + bias
// 128x128 CTA tile, BK=64 (SW128 rows), 8 warps 4(M)x2(N), m16n8k16 HMMA,
// cp.async double-buffered. grid = (M/128, Npad/128), bm fastest.
// ---------------------------------------------------------------------------
__device__ __forceinline__ uint32_t smem_u32(const void* p) {
    uint32_t a;
    asm("{ .reg .u64 t; cvta.to.shared.u64 t, %1; cvt.u32.u64 %0, t; }"
        : "=r"(a) : "l"(p));
    return a;
}
#define LDSM_X4(r0, r1, r2, r3, addr) \
    asm volatile("ldmatrix.sync.aligned.m8n8.x4.shared.b16 {%0,%1,%2,%3}, [%4];" \
        : "=r"(r0), "=r"(r1), "=r"(r2), "=r"(r3) : "r"(addr))
#define MMA16816(c, a0, a1, a2, a3, b0, b1) \
    asm volatile("mma.sync.aligned.m16n8k16.row.col.f32.bf16.bf16.f32 " \
        "{%0,%1,%2,%3}, {%4,%5,%6,%7}, {%8,%9}, {%0,%1,%2,%3};" \
        : "+f"((c)[0]), "+f"((c)[1]), "+f"((c)[2]), "+f"((c)[3]) \
        : "r"(a0), "r"(a1), "r"(a2), "r"(a3), "r"(b0), "r"(b1))
#define CP16(saddr, gptr) \
    asm volatile("cp.async.cg.shared.global [%0], [%1], 16;" \
        :: "r"(saddr), "l"(gptr))

#define MMA_SMEM 65536   // 2 bufs x (16KB A + 16KB B)

__global__ __launch_bounds__(256, 2) void gemm_mma(
    const __nv_bfloat16* __restrict__ A,
    const __nv_bfloat16* __restrict__ B,
    const float* __restrict__ bias, float* __restrict__ C,
    int K, int ldc, int ncols)
{
    extern __shared__ __align__(16) char smem_mma[];
    const uint32_t smb = smem_u32(smem_mma);

    const int tid = threadIdx.x;
    const int bm = blockIdx.x, bn = blockIdx.y;
    const int lane = tid & 31, wid = tid >> 5;
    const int wm = wid & 3, wn = wid >> 2;
    const int g = lane >> 3, l8 = lane & 7;

    float acc[2][8][4];
#pragma unroll
    for (int mt = 0; mt < 2; ++mt)
#pragma unroll
        for (int nt = 0; nt < 8; ++nt)
#pragma unroll
            for (int q = 0; q < 4; ++q) acc[mt][nt][q] = 0.f;

    const int arow0 = wm * 32 + (g & 1) * 8 + l8;
    const int aug   = g >> 1;
    const int brow0 = wn * 64 + (g >> 1) * 8 + l8;
    const int bug   = g & 1;

    const int lrow = tid >> 3, lunit = tid & 7;
    const __nv_bfloat16* Abase = A + (size_t)(bm * 128) * K;
    const __nv_bfloat16* Bbase = B + (size_t)(bn * 128) * K;

    int rowv[4];
    uint32_t soff[4];
#pragma unroll
    for (int i = 0; i < 4; ++i) {
        rowv[i] = lrow + i * 32;
        soff[i] = (uint32_t)rowv[i] * 128u
                + ((uint32_t)(lunit ^ (rowv[i] & 7)) << 4);
    }

    auto issue_chunk = [&](int kc, int buf) {
        const uint32_t ab = smb + (uint32_t)buf * 32768u;
        const uint32_t bb = ab + 16384u;
#pragma unroll
        for (int i = 0; i < 4; ++i) {
            CP16(ab + soff[i],
                 Abase + (size_t)rowv[i] * K + kc * 64 + lunit * 8);
            CP16(bb + soff[i],
                 Bbase + (size_t)rowv[i] * K + kc * 64 + lunit * 8);
        }
    };

    const int nchunks = K / 64;
    issue_chunk(0, 0);
    asm volatile("cp.async.commit_group;" ::: "memory");

    for (int kc = 0; kc < nchunks; ++kc) {
        const int buf = kc & 1;
        if (kc + 1 < nchunks) {
            issue_chunk(kc + 1, buf ^ 1);
            asm volatile("cp.async.commit_group;" ::: "memory");
            asm volatile("cp.async.wait_group 1;" ::: "memory");
        } else {
            asm volatile("cp.async.wait_group 0;" ::: "memory");
        }
        __syncthreads();

        const uint32_t asmb = smb + (uint32_t)buf * 32768u;
        const uint32_t bsmb = asmb + 16384u;
#pragma unroll
        for (int ks = 0; ks < 4; ++ks) {
            uint32_t a[2][4];
#pragma unroll
            for (int mt = 0; mt < 2; ++mt) {
                const int row = arow0 + mt * 16;
                const uint32_t addr = asmb + (uint32_t)row * 128u
                    + ((uint32_t)((ks * 2 + aug) ^ l8) << 4);
                LDSM_X4(a[mt][0], a[mt][1], a[mt][2], a[mt][3], addr);
            }
#pragma unroll
            for (int p = 0; p < 4; ++p) {
                const int row = brow0 + p * 16;
                const uint32_t addr = bsmb + (uint32_t)row * 128u
                    + ((uint32_t)((ks * 2 + bug) ^ l8) << 4);
                uint32_t b0, b1, b2, b3;
                LDSM_X4(b0, b1, b2, b3, addr);
                MMA16816(acc[0][2 * p],     a[0][0], a[0][1], a[0][2], a[0][3], b0, b1);
                MMA16816(acc[0][2 * p + 1], a[0][0], a[0][1], a[0][2], a[0][3], b2, b3);
                MMA16816(acc[1][2 * p],     a[1][0], a[1][1], a[1][2], a[1][3], b0, b1);
                MMA16816(acc[1][2 * p + 1], a[1][0], a[1][1], a[1][2], a[1][3], b2, b3);
            }
        }
        __syncthreads();
    }

    const int mrow = lane >> 2, nc2 = (lane & 3) * 2;
#pragma unroll
    for (int mt = 0; mt < 2; ++mt) {
        const int row0 = bm * 128 + wm * 32 + mt * 16 + mrow;
        float* c0 = C + (size_t)row0 * ldc;
        float* c1 = C + (size_t)(row0 + 8) * ldc;
#pragma unroll
        for (int nt = 0; nt < 8; ++nt) {
            const int col = bn * 128 + wn * 64 + nt * 8 + nc2;
            if (col < ncols) {
                const float bx = __ldg(bias + col);
                const float by = __ldg(bias + col + 1);
                *(float2*)(c0 + col) =
                    make_float2(acc[mt][nt][0] + bx, acc[mt][nt][1] + by);
                *(float2*)(c1 + col) =
                    make_float2(acc[mt][nt][2] + bx, acc[mt][nt][3] + by);
            }
        }
    }
}

// ---------------------------------------------------------------------------
// Persistent LSTM layer — EXACT R10 version (best measured).
// ---------------------------------------------------------------------------
#define WPAD 33
#define LSTM_SMEM_FLOATS (1024 * WPAD + 1024 * 4 + 256 * 4 + 128)
#define LSTM_SMEM_BYTES (LSTM_SMEM_FLOATS * 4)

__global__ __launch_bounds__(256) void lstm_layer(
    const float* __restrict__ xg,
    const float* __restrict__ Whh,
    float* __restrict__ hseq,
    float* __restrict__ hT)
{
    extern __shared__ float sm[];
    float*  Wsm  = sm;
    float4* hsm  = (float4*)(sm + 1024 * WPAD);
    float*  red  = (float*)(hsm + 1024);
    float*  gbuf = red + 1024;

    const int tid = threadIdx.x;
    const int cta = blockIdx.x;

    for (int i = tid; i < 32 * 1024; i += 256) {
        const int r = i >> 10, k = i & 1023;
        const int grow = (r >> 3) * HH + cta * 8 + (r & 7);
        Wsm[k * WPAD + r] = Whh[(size_t)grow * HH + k];
    }
    for (int i = tid; i < 1024; i += 256)
        hsm[i] = make_float4(0.f, 0.f, 0.f, 0.f);
    __syncthreads();

    const int row32 = tid & 31, kseg = tid >> 5;
    const int rrow = tid >> 2, rb = tid & 3;
    float cstate = 0.f;

    for (int t = 0; t < TT; ++t) {
        float xval = 0.f;
        if (tid < 128) {
            const int grow = (rrow >> 3) * HH + cta * 8 + (rrow & 7);
            xval = __ldg(&xg[((size_t)(rb * TT + t)) * GG + grow]);
        }

        float4 p = make_float4(0.f, 0.f, 0.f, 0.f);
        const float*  wp = &Wsm[(kseg * 128) * WPAD + row32];
        const float4* hp = &hsm[kseg * 128];
#pragma unroll 8
        for (int k = 0; k < 128; ++k) {
            const float  w  = wp[k * WPAD];
            const float4 h4 = hp[k];
            p.x += w * h4.x; p.y += w * h4.y;
            p.z += w * h4.z; p.w += w * h4.w;
        }
        ((float4*)red)[tid] = p;
        __syncthreads();

        if (tid < 128) {
            float s = xval;
#pragma unroll
            for (int sg = 0; sg < 8; ++sg)
                s += red[(sg * 32 + rrow) * 4 + rb];
            gbuf[rrow * 4 + rb] = s;
        }
        __syncthreads();

        if (tid < 32) {
            const int gu = tid >> 2, gb = tid & 3;
            float gi = gbuf[(0 * 8 + gu) * 4 + gb];
            float gf = gbuf[(1 * 8 + gu) * 4 + gb];
            float gg = gbuf[(2 * 8 + gu) * 4 + gb];
            float go = gbuf[(3 * 8 + gu) * 4 + gb];
            gi = 1.f / (1.f + __expf(-gi));
            gf = 1.f / (1.f + __expf(-gf));
            gg = tanhf(gg);
            go = 1.f / (1.f + __expf(-go));
            cstate = gf * cstate + gi * gg;
            const float h = go * tanhf(cstate);
            const int unit = cta * 8 + gu;
            hseq[((size_t)(gb * TT + t)) * HH + unit] = h;
            __stcg(&hT[(t & 1) * (HH * 4) + unit * 4 + gb], h);
        }

        __threadfence();
        __syncthreads();
        if (tid == 0) {
            atomicAdd(&g_cnt, 1u);
            const unsigned target = (unsigned)NCTA * (unsigned)(t + 1);
            unsigned v;
            do {
                asm volatile("ld.global.cg.u32 %0, [%1];"
                             : "=r"(v) : "l"(&g_cnt));
            } while (v < target);
        }
        __syncthreads();

        const float4* src = (const float4*)&hT[(t & 1) * (HH * 4)];
        for (int i = tid; i < 1024; i += 256)
            hsm[i] = __ldcg(src + i);
        __syncthreads();
    }
}

// ---------------------------------------------------------------------------
// log-softmax
// ---------------------------------------------------------------------------
__global__ __launch_bounds__(256) void rowstats(
    const float* __restrict__ logits, float* __restrict__ lse)
{
    const int row = blockIdx.x, tid = threadIdx.x;
    const float4* p = (const float4*)(logits + (size_t)row * VV);
    float m = -1e30f, s = 0.f;
    for (int i = tid; i < VV / 4; i += 256) {
        const float4 v = p[i];
        const float vm = fmaxf(fmaxf(v.x, v.y), fmaxf(v.z, v.w));
        if (vm > m) { s *= __expf(m - vm); m = vm; }
        s += __expf(v.x - m) + __expf(v.y - m) +
             __expf(v.z - m) + __expf(v.w - m);
    }
    __shared__ float sm_m[256], sm_s[256];
    sm_m[tid] = m; sm_s[tid] = s;
    __syncthreads();
    for (int off = 128; off > 0; off >>= 1) {
        if (tid < off) {
            const float m2 = sm_m[tid + off], s2 = sm_s[tid + off];
            const float mm = fmaxf(sm_m[tid], m2);
            sm_s[tid] = sm_s[tid] * __expf(sm_m[tid] - mm) + s2 * __expf(m2 - mm);
            sm_m[tid] = mm;
        }
        __syncthreads();
    }
    if (tid == 0) lse[row] = sm_m[0] + __logf(sm_s[0]);
}

__global__ __launch_bounds__(256) void finalize_ls(
    float* __restrict__ out, const float* __restrict__ lse)
{
    const size_t i = (size_t)blockIdx.x * 256 + threadIdx.x;
    const size_t total = (size_t)BT * VV / 4;
    if (i < total) {
        const int row = (int)((i * 4) / VV);
        const float l = lse[row];
        float4 v = ((float4*)out)[i];
        v.x -= l; v.y -= l; v.z -= l; v.w -= l;
        ((float4*)out)[i] = v;
    }
}

// ---------------------------------------------------------------------------
extern "C" void kernel_launch(void* const* d_in, const int* in_sizes, int n_in,
                              void* d_out, int out_size)
{
    const int*   token_idx = (const int*)  d_in[0];
    const float* X         = (const float*)d_in[1];
    const float* W_ih0     = (const float*)d_in[2];
    const float* W_hh0     = (const float*)d_in[3];
    const float* b0        = (const float*)d_in[4];
    const float* W_ih1     = (const float*)d_in[5];
    const float* W_hh1     = (const float*)d_in[6];
    const float* b1        = (const float*)d_in[7];
    const float* W_out     = (const float*)d_in[8];
    const float* b_out     = (const float*)d_in[9];
    float* out = (float*)d_out;

    float* xg = nullptr;  cudaGetSymbolAddress((void**)&xg, g_xg);
    float* h0 = nullptr;  cudaGetSymbolAddress((void**)&h0, g_h0);
    float* h1 = nullptr;  cudaGetSymbolAddress((void**)&h1, g_h1);
    float* hT = nullptr;  cudaGetSymbolAddress((void**)&hT, g_hT);
    float* lse = nullptr; cudaGetSymbolAddress((void**)&lse, g_lse);
    __nv_bfloat16* wb   = nullptr; cudaGetSymbolAddress((void**)&wb,   g_wb);
    __nv_bfloat16* hb   = nullptr; cudaGetSymbolAddress((void**)&hb,   g_hb);
    __nv_bfloat16* h0b  = nullptr; cudaGetSymbolAddress((void**)&h0b,  g_h0b);
    __nv_bfloat16* wi0b = nullptr; cudaGetSymbolAddress((void**)&wi0b, g_wi0b);
    __nv_bfloat16* wi1b = nullptr; cudaGetSymbolAddress((void**)&wi1b, g_wi1b);
    __nv_bfloat16* embB = nullptr; cudaGetSymbolAddress((void**)&embB, g_embB);

    cudaFuncSetAttribute(lstm_layer,
        cudaFuncAttributeMaxDynamicSharedMemorySize, LSTM_SMEM_BYTES);
    cudaFuncSetAttribute(gemm_mma,
        cudaFuncAttributeMaxDynamicSharedMemorySize, MMA_SMEM);

    // conversions (W_out / W_ih0 / W_ih1 independent of LSTM chain)
    {
        const size_t nsrc = (size_t)VV * HH, ntot = (size_t)VPAD * HH;
        conv_bf16<<<(unsigned)((ntot / 4 + 255) / 256), 256>>>(W_out, wb, nsrc, ntot);
        const size_t n0 = (size_t)GG * DD;
        conv_bf16<<<(unsigned)((n0 / 4 + 255) / 256), 256>>>(W_ih0, wi0b, n0, n0);
        const size_t n1 = (size_t)GG * HH;
        conv_bf16<<<(unsigned)((n1 / 4 + 255) / 256), 256>>>(W_ih1, wi1b, n1, n1);
    }
    gather_emb<<<(unsigned)(((size_t)BT * DD / 4 + 255) / 256), 256>>>(
        token_idx, X, embB);

    // K1: xg0 = emb @ W_ih0^T + b0  (HMMA, K=512)
    gemm_mma<<<dim3(BT / 128, GG / 128), 256, MMA_SMEM>>>(
        embB, wi0b, b0, xg, DD, GG, GG);

    reset_bar<<<1, 1>>>();
    lstm_layer<<<NCTA, 256, LSTM_SMEM_BYTES>>>(xg, W_hh0, h0, hT);

    // h0 -> bf16, then K3: xg1 = h0 @ W_ih1^T + b1 (HMMA, K=1024)
    {
        const size_t n = (size_t)BT * HH;
        conv_bf16<<<(unsigned)((n / 4 + 255) / 256), 256>>>(h0, h0b, n, n);
    }
    gemm_mma<<<dim3(BT / 128, GG / 128), 256, MMA_SMEM>>>(
        h0b, wi1b, b1, xg, HH, GG, GG);

    reset_bar<<<1, 1>>>();
    lstm_layer<<<NCTA, 256, LSTM_SMEM_BYTES>>>(xg, W_hh1, h1, hT);

    // h1 -> bf16
    {
        const size_t n = (size_t)BT * HH;
        conv_bf16<<<(unsigned)((n / 4 + 255) / 256), 256>>>(h1, hb, n, n);
    }

    // K5: logits = h1 @ W_out^T + b_out (HMMA)
    gemm_mma<<<dim3(BT / 128, VPAD / 128), 256, MMA_SMEM>>>(
        hb, wb, b_out, out, HH, VV, VV);

    rowstats<<<BT, 256>>>(out, lse);
    const size_t total4 = (size_t)BT * VV / 4;
    finalize_ls<<<(unsigned)((total4 + 255) / 256), 256>>>(out, lse);
}

// round 15
// speedup vs baseline: 2.5331x; 1.0177x over previous
#include <cuda_runtime.h>
#include <cuda_bf16.h>
#include <cstdint>
#include <cstddef>
#include <math.h>

#define BQ 4
#define TT 512
#define BT (BQ * TT)      // 2048
#define DD 512
#define HH 1024
#define GG (4 * HH)       // 4096
#define VV 50000
#define VPAD 50048        // 391 * 128
#define NCTA 128          // persistent LSTM CTAs

using ull = unsigned long long;

// ---------------- device scratch ----------------
__device__ float g_xg[(size_t)BT * GG];
__device__ float g_lse[BT];
__device__ unsigned g_cnt;
__device__ __nv_bfloat16 g_wb[(size_t)VPAD * HH];    // bf16 W_out (padded)
__device__ __nv_bfloat16 g_h0b[(size_t)BT * HH];     // bf16 h0 seq
__device__ __nv_bfloat16 g_h1b[(size_t)BT * HH];     // bf16 h1 seq
__device__ __nv_bfloat16 g_wi0b[(size_t)GG * DD];    // bf16 W_ih0
__device__ __nv_bfloat16 g_wi1b[(size_t)GG * HH];    // bf16 W_ih1
__device__ __nv_bfloat16 g_embB[(size_t)BT * DD];    // bf16 gathered emb
__device__ __nv_bfloat16 g_hTb[2 * BQ * HH];         // bf16 h ping-pong

__global__ void reset_bar() { g_cnt = 0u; }

// ---------------------------------------------------------------------------
// f32 -> bf16 conversion (zero-pads tail for W_out)
// ---------------------------------------------------------------------------
__global__ __launch_bounds__(256) void conv_bf16(
    const float* __restrict__ src, __nv_bfloat16* __restrict__ dst,
    size_t n_src, size_t n_total)
{
    const size_t i = ((size_t)blockIdx.x * 256 + threadIdx.x) * 4;
    if (i >= n_total) return;
    uint2 o;
    if (i < n_src) {
        const float4 v = *(const float4*)(src + i);
        __nv_bfloat162 lo = __floats2bfloat162_rn(v.x, v.y);
        __nv_bfloat162 hi = __floats2bfloat162_rn(v.z, v.w);
        o.x = *(unsigned*)&lo;
        o.y = *(unsigned*)&hi;
    } else {
        o.x = 0u; o.y = 0u;
    }
    *(uint2*)(dst + i) = o;
}

// gather token embeddings and convert to bf16
__global__ __launch_bounds__(256) void gather_emb(
    const int* __restrict__ tok, const float* __restrict__ X,
    __nv_bfloat16* __restrict__ dst)
{
    const size_t i = ((size_t)blockIdx.x * 256 + threadIdx.x) * 4;
    if (i >= (size_t)BT * DD) return;
    const int row = (int)(i >> 9);
    const int col = (int)(i & (DD - 1));
    const float4 v = *(const float4*)(X + (size_t)tok[row] * DD + col);
    __nv_bfloat162 lo = __floats2bfloat162_rn(v.x, v.y);
    __nv_bfloat162 hi = __floats2bfloat162_rn(v.z, v.w);
    uint2 o;
    o.x = *(unsigned*)&lo;
    o.y = *(unsigned*)&hi;
    *(uint2*)(dst + i) = o;
}

// ---------------------------------------------------------------------------
// mma.sync bf16 GEMM (generalized): C[M, ldc] = A[M,K].B[Npad,K]^T + bias
// ---------------------------------------------------------------------------
__device__ __forceinline__ uint32_t smem_u32(const void* p) {
    uint32_t a;
    asm("{ .reg .u64 t; cvta.to.shared.u64 t, %1; cvt.u32.u64 %0, t; }"
        : "=r"(a) : "l"(p));
    return a;
}
#define LDSM_X4(r0, r1, r2, r3, addr) \
    asm volatile("ldmatrix.sync.aligned.m8n8.x4.shared.b16 {%0,%1,%2,%3}, [%4];" \
        : "=r"(r0), "=r"(r1), "=r"(r2), "=r"(r3) : "r"(addr))
#define MMA16816(c, a0, a1, a2, a3, b0, b1) \
    asm volatile("mma.sync.aligned.m16n8k16.row.col.f32.bf16.bf16.f32 " \
        "{%0,%1,%2,%3}, {%4,%5,%6,%7}, {%8,%9}, {%0,%1,%2,%3};" \
        : "+f"((c)[0]), "+f"((c)[1]), "+f"((c)[2]), "+f"((c)[3]) \
        : "r"(a0), "r"(a1), "r"(a2), "r"(a3), "r"(b0), "r"(b1))
#define CP16(saddr, gptr) \
    asm volatile("cp.async.cg.shared.global [%0], [%1], 16;" \
        :: "r"(saddr), "l"(gptr))

#define MMA_SMEM 65536

__global__ __launch_bounds__(256, 2) void gemm_mma(
    const __nv_bfloat16* __restrict__ A,
    const __nv_bfloat16* __restrict__ B,
    const float* __restrict__ bias, float* __restrict__ C,
    int K, int ldc, int ncols)
{
    extern __shared__ __align__(16) char smem_mma[];
    const uint32_t smb = smem_u32(smem_mma);

    const int tid = threadIdx.x;
    const int bm = blockIdx.x, bn = blockIdx.y;
    const int lane = tid & 31, wid = tid >> 5;
    const int wm = wid & 3, wn = wid >> 2;
    const int g = lane >> 3, l8 = lane & 7;

    float acc[2][8][4];
#pragma unroll
    for (int mt = 0; mt < 2; ++mt)
#pragma unroll
        for (int nt = 0; nt < 8; ++nt)
#pragma unroll
            for (int q = 0; q < 4; ++q) acc[mt][nt][q] = 0.f;

    const int arow0 = wm * 32 + (g & 1) * 8 + l8;
    const int aug   = g >> 1;
    const int brow0 = wn * 64 + (g >> 1) * 8 + l8;
    const int bug   = g & 1;

    const int lrow = tid >> 3, lunit = tid & 7;
    const __nv_bfloat16* Abase = A + (size_t)(bm * 128) * K;
    const __nv_bfloat16* Bbase = B + (size_t)(bn * 128) * K;

    int rowv[4];
    uint32_t soff[4];
#pragma unroll
    for (int i = 0; i < 4; ++i) {
        rowv[i] = lrow + i * 32;
        soff[i] = (uint32_t)rowv[i] * 128u
                + ((uint32_t)(lunit ^ (rowv[i] & 7)) << 4);
    }

    auto issue_chunk = [&](int kc, int buf) {
        const uint32_t ab = smb + (uint32_t)buf * 32768u;
        const uint32_t bb = ab + 16384u;
#pragma unroll
        for (int i = 0; i < 4; ++i) {
            CP16(ab + soff[i],
                 Abase + (size_t)rowv[i] * K + kc * 64 + lunit * 8);
            CP16(bb + soff[i],
                 Bbase + (size_t)rowv[i] * K + kc * 64 + lunit * 8);
        }
    };

    const int nchunks = K / 64;
    issue_chunk(0, 0);
    asm volatile("cp.async.commit_group;" ::: "memory");

    for (int kc = 0; kc < nchunks; ++kc) {
        const int buf = kc & 1;
        if (kc + 1 < nchunks) {
            issue_chunk(kc + 1, buf ^ 1);
            asm volatile("cp.async.commit_group;" ::: "memory");
            asm volatile("cp.async.wait_group 1;" ::: "memory");
        } else {
            asm volatile("cp.async.wait_group 0;" ::: "memory");
        }
        __syncthreads();

        const uint32_t asmb = smb + (uint32_t)buf * 32768u;
        const uint32_t bsmb = asmb + 16384u;
#pragma unroll
        for (int ks = 0; ks < 4; ++ks) {
            uint32_t a[2][4];
#pragma unroll
            for (int mt = 0; mt < 2; ++mt) {
                const int row = arow0 + mt * 16;
                const uint32_t addr = asmb + (uint32_t)row * 128u
                    + ((uint32_t)((ks * 2 + aug) ^ l8) << 4);
                LDSM_X4(a[mt][0], a[mt][1], a[mt][2], a[mt][3], addr);
            }
#pragma unroll
            for (int p = 0; p < 4; ++p) {
                const int row = brow0 + p * 16;
                const uint32_t addr = bsmb + (uint32_t)row * 128u
                    + ((uint32_t)((ks * 2 + bug) ^ l8) << 4);
                uint32_t b0, b1, b2, b3;
                LDSM_X4(b0, b1, b2, b3, addr);
                MMA16816(acc[0][2 * p],     a[0][0], a[0][1], a[0][2], a[0][3], b0, b1);
                MMA16816(acc[0][2 * p + 1], a[0][0], a[0][1], a[0][2], a[0][3], b2, b3);
                MMA16816(acc[1][2 * p],     a[1][0], a[1][1], a[1][2], a[1][3], b0, b1);
                MMA16816(acc[1][2 * p + 1], a[1][0], a[1][1], a[1][2], a[1][3], b2, b3);
            }
        }
        __syncthreads();
    }

    const int mrow = lane >> 2, nc2 = (lane & 3) * 2;
#pragma unroll
    for (int mt = 0; mt < 2; ++mt) {
        const int row0 = bm * 128 + wm * 32 + mt * 16 + mrow;
        float* c0 = C + (size_t)row0 * ldc;
        float* c1 = C + (size_t)(row0 + 8) * ldc;
#pragma unroll
        for (int nt = 0; nt < 8; ++nt) {
            const int col = bn * 128 + wn * 64 + nt * 8 + nc2;
            if (col < ncols) {
                const float bx = __ldg(bias + col);
                const float by = __ldg(bias + col + 1);
                *(float2*)(c0 + col) =
                    make_float2(acc[mt][nt][0] + bx, acc[mt][nt][1] + by);
                *(float2*)(c1 + col) =
                    make_float2(acc[mt][nt][2] + bx, acc[mt][nt][3] + by);
            }
        }
    }
}

// ---------------------------------------------------------------------------
// Persistent LSTM layer with HMMA recurrence dot.
// CTA owns 32 gate rows (8 units x 4 gates). W slice bf16 in SMEM (64KB,
// 2048B rows, 128B-block XOR swizzle). h bf16 in 16-row SMEM tile (rows 0-3
// = batches, rows 4-15 zero). 8 warps = 2 n16-groups x 4 K-quarters.
// R10 barrier (atomic arrival + tid0 relaxed poll).
// ---------------------------------------------------------------------------
#define LSTM_SMEM_BYTES (65536 + 32768 + 2560 + 512 + 128)

__device__ __forceinline__ uint32_t sw2k(int row, int u16) {
    return (uint32_t)row * 2048u + (uint32_t)((u16 >> 3) << 7)
         + (uint32_t)((((u16 & 7) ^ (row & 7))) << 4);
}

__global__ __launch_bounds__(256) void lstm_layer(
    const float* __restrict__ xg,          // [BT][4096] f32
    const float* __restrict__ Whh,         // [4096][1024] f32
    __nv_bfloat16* __restrict__ hseqb,     // [BT][1024] bf16 out
    __nv_bfloat16* __restrict__ hTb)       // [2][4][1024] bf16 ping-pong
{
    extern __shared__ __align__(16) char sml[];
    char*  Wsm  = sml;                     // 32 x 2048B
    char*  hsm  = sml + 65536;             // 16 x 2048B
    float* red  = (float*)(sml + 98304);   // [32 colg][20] (batch*5+kq)
    float* gbuf = (float*)(sml + 100864);  // 128

    const int tid = threadIdx.x, cta = blockIdx.x;
    const int lane = tid & 31, wid = tid >> 5;

    // stage W slice: f32 -> bf16, swizzled
    for (int i = tid; i < 32 * 256; i += 256) {
        const int r = i >> 8, k = (i & 255) * 4;
        const int grow = (r >> 3) * HH + cta * 8 + (r & 7);
        const float4 w4 = *(const float4*)(Whh + (size_t)grow * HH + k);
        __nv_bfloat162 lo = __floats2bfloat162_rn(w4.x, w4.y);
        __nv_bfloat162 hi = __floats2bfloat162_rn(w4.z, w4.w);
        uint2 o; o.x = *(unsigned*)&lo; o.y = *(unsigned*)&hi;
        const uint32_t soff = sw2k(r, k >> 3) + (uint32_t)(((k >> 2) & 1) * 8);
        *(uint2*)(Wsm + soff) = o;
    }
    // zero h tile (incl. padding rows 4-15)
    for (int i = tid; i < 2048; i += 256)
        ((uint4*)hsm)[i] = make_uint4(0u, 0u, 0u, 0u);
    __syncthreads();

    const int g = lane >> 3, l8 = lane & 7;
    const int ngrp = wid & 1, kq = wid >> 1;
    const int arow = (g & 1) * 8 + l8, au = g >> 1;
    const int brow = ngrp * 16 + (g >> 1) * 8 + l8, bu = g & 1;
    const uint32_t hsmB = smem_u32(hsm);
    const uint32_t WsmB = smem_u32(Wsm);
    float cstate = 0.f;

    for (int t = 0; t < TT; ++t) {
        // prefetch xg (latency hidden under the dot)
        float xval = 0.f;
        if (tid < 128) {
            const int colg = tid >> 2, rb = tid & 3;
            const int grow = (colg >> 3) * HH + cta * 8 + (colg & 7);
            xval = __ldg(&xg[((size_t)(rb * TT + t)) * GG + grow]);
        }

        // HMMA dot: [4 x 1024] x [32 x 1024]^T, this warp: n16 x K/4
        float acc0[4] = {0.f, 0.f, 0.f, 0.f};
        float acc1[4] = {0.f, 0.f, 0.f, 0.f};
#pragma unroll
        for (int ks = 0; ks < 16; ++ks) {
            const int kg = kq * 16 + ks;
            uint32_t a0, a1, a2, a3;
            LDSM_X4(a0, a1, a2, a3, hsmB + sw2k(arow, kg * 2 + au));
            uint32_t b0, b1, b2, b3;
            LDSM_X4(b0, b1, b2, b3, WsmB + sw2k(brow, kg * 2 + bu));
            MMA16816(acc0, a0, a1, a2, a3, b0, b1);
            MMA16816(acc1, a0, a1, a2, a3, b2, b3);
        }
        if (lane < 16) {               // rows 0-3 = batches hold valid c0,c1
            const int batch = lane >> 2, c2 = (lane & 3) * 2;
            const int cg0 = ngrp * 16 + c2;
            red[cg0 * 20 + batch * 5 + kq]       = acc0[0];
            red[(cg0 + 1) * 20 + batch * 5 + kq] = acc0[1];
            const int cg1 = ngrp * 16 + 8 + c2;
            red[cg1 * 20 + batch * 5 + kq]       = acc1[0];
            red[(cg1 + 1) * 20 + batch * 5 + kq] = acc1[1];
        }
        __syncthreads();

        if (tid < 128) {
            const int colg = tid >> 2, batch = tid & 3;
            float s = xval;
#pragma unroll
            for (int q = 0; q < 4; ++q)
                s += red[colg * 20 + batch * 5 + q];
            gbuf[tid] = s;
        }
        __syncthreads();

        if (tid < 32) {
            const int gu = tid >> 2, gb = tid & 3;
            float gi = gbuf[(0 * 8 + gu) * 4 + gb];
            float gf = gbuf[(1 * 8 + gu) * 4 + gb];
            float gg = gbuf[(2 * 8 + gu) * 4 + gb];
            float go = gbuf[(3 * 8 + gu) * 4 + gb];
            gi = 1.f / (1.f + __expf(-gi));
            gf = 1.f / (1.f + __expf(-gf));
            gg = tanhf(gg);
            go = 1.f / (1.f + __expf(-go));
            cstate = gf * cstate + gi * gg;
            const float h = go * tanhf(cstate);
            const int unit = cta * 8 + gu;
            const __nv_bfloat16 hb16 = __float2bfloat16(h);
            hseqb[((size_t)(gb * TT + t)) * HH + unit] = hb16;
            hTb[(t & 1) * (BQ * HH) + gb * HH + unit] = hb16;
        }

        // grid barrier (R10): atomic arrival + single-thread relaxed poll
        __threadfence();
        __syncthreads();
        if (tid == 0) {
            atomicAdd(&g_cnt, 1u);
            const unsigned target = (unsigned)NCTA * (unsigned)(t + 1);
            unsigned v;
            do {
                asm volatile("ld.global.cg.u32 %0, [%1];"
                             : "=r"(v) : "l"(&g_cnt));
            } while (v < target);
        }
        __syncthreads();

        // reload h tile rows 0-3 (bf16, 8KB), L1-bypassed
        {
            const uint4* src = (const uint4*)(hTb + (t & 1) * (BQ * HH));
            for (int i = tid; i < 512; i += 256) {
                const int row = i >> 7, u16 = i & 127;
                const uint4 v = __ldcg(src + i);
                *(uint4*)(hsm + sw2k(row, u16)) = v;
            }
        }
        __syncthreads();
    }
}

// ---------------------------------------------------------------------------
// log-softmax
// ---------------------------------------------------------------------------
__global__ __launch_bounds__(256) void rowstats(
    const float* __restrict__ logits, float* __restrict__ lse)
{
    const int row = blockIdx.x, tid = threadIdx.x;
    const float4* p = (const float4*)(logits + (size_t)row * VV);
    float m = -1e30f, s = 0.f;
    for (int i = tid; i < VV / 4; i += 256) {
        const float4 v = p[i];
        const float vm = fmaxf(fmaxf(v.x, v.y), fmaxf(v.z, v.w));
        if (vm > m) { s *= __expf(m - vm); m = vm; }
        s += __expf(v.x - m) + __expf(v.y - m) +
             __expf(v.z - m) + __expf(v.w - m);
    }
    __shared__ float sm_m[256], sm_s[256];
    sm_m[tid] = m; sm_s[tid] = s;
    __syncthreads();
    for (int off = 128; off > 0; off >>= 1) {
        if (tid < off) {
            const float m2 = sm_m[tid + off], s2 = sm_s[tid + off];
            const float mm = fmaxf(sm_m[tid], m2);
            sm_s[tid] = sm_s[tid] * __expf(sm_m[tid] - mm) + s2 * __expf(m2 - mm);
            sm_m[tid] = mm;
        }
        __syncthreads();
    }
    if (tid == 0) lse[row] = sm_m[0] + __logf(sm_s[0]);
}

__global__ __launch_bounds__(256) void finalize_ls(
    float* __restrict__ out, const float* __restrict__ lse)
{
    const size_t i = (size_t)blockIdx.x * 256 + threadIdx.x;
    const size_t total = (size_t)BT * VV / 4;
    if (i < total) {
        const int row = (int)((i * 4) / VV);
        const float l = lse[row];
        float4 v = ((float4*)out)[i];
        v.x -= l; v.y -= l; v.z -= l; v.w -= l;
        ((float4*)out)[i] = v;
    }
}

// ---------------------------------------------------------------------------
extern "C" void kernel_launch(void* const* d_in, const int* in_sizes, int n_in,
                              void* d_out, int out_size)
{
    const int*   token_idx = (const int*)  d_in[0];
    const float* X         = (const float*)d_in[1];
    const float* W_ih0     = (const float*)d_in[2];
    const float* W_hh0     = (const float*)d_in[3];
    const float* b0        = (const float*)d_in[4];
    const float* W_ih1     = (const float*)d_in[5];
    const float* W_hh1     = (const float*)d_in[6];
    const float* b1        = (const float*)d_in[7];
    const float* W_out     = (const float*)d_in[8];
    const float* b_out     = (const float*)d_in[9];
    float* out = (float*)d_out;

    float* xg = nullptr;  cudaGetSymbolAddress((void**)&xg, g_xg);
    float* lse = nullptr; cudaGetSymbolAddress((void**)&lse, g_lse);
    __nv_bfloat16* wb   = nullptr; cudaGetSymbolAddress((void**)&wb,   g_wb);
    __nv_bfloat16* h0b  = nullptr; cudaGetSymbolAddress((void**)&h0b,  g_h0b);
    __nv_bfloat16* h1b  = nullptr; cudaGetSymbolAddress((void**)&h1b,  g_h1b);
    __nv_bfloat16* wi0b = nullptr; cudaGetSymbolAddress((void**)&wi0b, g_wi0b);
    __nv_bfloat16* wi1b = nullptr; cudaGetSymbolAddress((void**)&wi1b, g_wi1b);
    __nv_bfloat16* embB = nullptr; cudaGetSymbolAddress((void**)&embB, g_embB);
    __nv_bfloat16* hTb  = nullptr; cudaGetSymbolAddress((void**)&hTb,  g_hTb);

    cudaFuncSetAttribute(lstm_layer,
        cudaFuncAttributeMaxDynamicSharedMemorySize, LSTM_SMEM_BYTES);
    cudaFuncSetAttribute(gemm_mma,
        cudaFuncAttributeMaxDynamicSharedMemorySize, MMA_SMEM);

    // weight conversions (independent of LSTM chain)
    {
        const size_t nsrc = (size_t)VV * HH, ntot = (size_t)VPAD * HH;
        conv_bf16<<<(unsigned)((ntot / 4 + 255) / 256), 256>>>(W_out, wb, nsrc, ntot);
        const size_t n0 = (size_t)GG * DD;
        conv_bf16<<<(unsigned)((n0 / 4 + 255) / 256), 256>>>(W_ih0, wi0b, n0, n0);
        const size_t n1 = (size_t)GG * HH;
        conv_bf16<<<(unsigned)((n1 / 4 + 255) / 256), 256>>>(W_ih1, wi1b, n1, n1);
    }
    gather_emb<<<(unsigned)(((size_t)BT * DD / 4 + 255) / 256), 256>>>(
        token_idx, X, embB);

    // K1: xg0 = emb @ W_ih0^T + b0  (HMMA, K=512)
    gemm_mma<<<dim3(BT / 128, GG / 128), 256, MMA_SMEM>>>(
        embB, wi0b, b0, xg, DD, GG, GG);

    reset_bar<<<1, 1>>>();
    lstm_layer<<<NCTA, 256, LSTM_SMEM_BYTES>>>(xg, W_hh0, h0b, hTb);

    // K3: xg1 = h0 @ W_ih1^T + b1 (HMMA, K=1024; h0 already bf16)
    gemm_mma<<<dim3(BT / 128, GG / 128), 256, MMA_SMEM>>>(
        h0b, wi1b, b1, xg, HH, GG, GG);

    reset_bar<<<1, 1>>>();
    lstm_layer<<<NCTA, 256, LSTM_SMEM_BYTES>>>(xg, W_hh1, h1b, hTb);

    // K5: logits = h1 @ W_out^T + b_out (HMMA)
    gemm_mma<<<dim3(BT / 128, VPAD / 128), 256, MMA_SMEM>>>(
        h1b, wb, b_out, out, HH, VV, VV);

    rowstats<<<BT, 256>>>(out, lse);
    const size_t total4 = (size_t)BT * VV / 4;
    finalize_ls<<<(unsigned)((total4 + 255) / 256), 256>>>(out, lse);
}